// round 1
// baseline (speedup 1.0000x reference)
#include <cuda_runtime.h>
#include <cstdint>

#define Q     65536
#define HH    256
#define WW    256
#define CIN   32
#define MROWS (4*Q)      /* 262144 */
#define K1    292
#define K1P   304
#define NHID  256

typedef unsigned long long u64;

// ---------------- scratch (device globals; no allocation allowed) ----------
__device__ float g_X [(size_t)MROWS * K1P];   // ~319 MB
__device__ float g_HA[(size_t)MROWS * NHID];  // ~268 MB
__device__ float g_HB[(size_t)MROWS * NHID];  // ~268 MB
__device__ float g_W1p[K1P * NHID];
__device__ float g_AREA[MROWS];

// ---------------- packed f32x2 FMA (Blackwell FFMA2) -----------------------
__device__ __forceinline__ void fma2(u64 &d, u64 a, u64 b) {
    asm("fma.rn.f32x2 %0, %1, %2, %0;" : "+l"(d) : "l"(a), "l"(b));
}

// ---------------- pad W1 to 304 rows ---------------------------------------
__global__ void pad_w1_kernel(const float* __restrict__ w1) {
    int i = blockIdx.x * 256 + threadIdx.x;
    if (i < K1P * NHID) {
        int k = i / NHID;
        g_W1p[i] = (k < K1) ? w1[(size_t)k * NHID + (i - k * NHID)] : 0.f;
    }
}

// ---------------- gather: build X rows + area weights ----------------------
__global__ void gather_kernel(const float* __restrict__ F,
                              const float* __restrict__ loc,
                              const float* __restrict__ cell) {
    const int q = blockIdx.x;   // query
    const int s = blockIdx.y;   // shift
    const int t = threadIdx.x;  // 0..303

    __shared__ int   s_iy, s_ix;
    __shared__ float s_rel0, s_rel1, s_c0, s_c1;

    if (t == 0) {
        float l0 = loc[(size_t)q * 2 + 0];
        float l1 = loc[(size_t)q * 2 + 1];
        float sy = (s & 2) ? 1.f : -1.f;
        float sx = (s & 1) ? 1.f : -1.f;
        float ly = l0 + sy * (1.f / HH) + 1e-6f;
        float lx = l1 + sx * (1.f / WW) + 1e-6f;
        ly = fminf(fmaxf(ly, -1.f + 1e-6f), 1.f - 1e-6f);
        lx = fminf(fmaxf(lx, -1.f + 1e-6f), 1.f - 1e-6f);
        int iy = (int)rintf(((ly + 1.f) * HH - 1.f) * 0.5f);
        int ix = (int)rintf(((lx + 1.f) * WW - 1.f) * 0.5f);
        iy = min(max(iy, 0), HH - 1);
        ix = min(max(ix, 0), WW - 1);
        float qy = -1.f + (2.f * iy + 1.f) / HH;
        float qx = -1.f + (2.f * ix + 1.f) / WW;
        s_iy = iy; s_ix = ix;
        s_rel0 = (l0 - qy) * HH;
        s_rel1 = (l1 - qx) * WW;
        s_c0 = cell[(size_t)q * 2 + 0] * HH;
        s_c1 = cell[(size_t)q * 2 + 1] * WW;
    }
    __syncthreads();

    const size_t row = (size_t)s * Q + q;
    float v;
    if (t < 288) {
        int c  = t / 9;
        int k  = t - c * 9;
        int di = k / 3;
        int dj = k - di * 3;
        int y = s_iy + di - 1;
        int x = s_ix + dj - 1;
        y = (y < 0) ? -y : ((y >= HH) ? 2 * HH - 2 - y : y);
        x = (x < 0) ? -x : ((x >= WW) ? 2 * WW - 2 - x : x);
        v = F[(size_t)c * (HH * WW) + y * WW + x];
    } else if (t == 288) v = s_rel0;
    else if   (t == 289) v = s_rel1;
    else if   (t == 290) v = s_c0;
    else if   (t == 291) v = s_c1;
    else                 v = 0.f;   // pad cols 292..303

    g_X[row * K1P + t] = v;
    if (t == 288) g_AREA[row] = fabsf(s_rel0 * s_rel1) + 1e-9f;
}

// ---------------- tiled GEMM + bias + ReLU, packed f32x2 -------------------
// C[M,256] = act(A[M,K] @ W[K,256] + b)   BM=128 BN=64 BK=16, 256 thr
template<int K, bool RELU>
__global__ __launch_bounds__(256)
void gemm_kernel(const float* __restrict__ A, const float* __restrict__ W,
                 const float* __restrict__ b, float* __restrict__ C) {
    __shared__ __align__(16) float As [16][128];
    __shared__ __align__(16) float Ws2[16][128];   // W duplicated per column

    const int tid = threadIdx.x;
    const int m0  = blockIdx.x * 128;
    const int n0  = blockIdx.y * 64;
    const int tx  = tid & 15;      // column group -> cols n0 + tx*4 .. +3
    const int ty  = tid >> 4;      // row group    -> rows m0 + ty*8 .. +7

    u64 acc[4][4];
#pragma unroll
    for (int p = 0; p < 4; ++p)
#pragma unroll
        for (int c = 0; c < 4; ++c) acc[p][c] = 0ull;

    const int arow = tid >> 2;     // 0..63
    const int avec = tid & 3;      // float4 idx within 16-wide k

    for (int k0 = 0; k0 < K; k0 += 16) {
        // A tile 128x16 -> As[k][row]
#pragma unroll
        for (int rr = 0; rr < 2; ++rr) {
            int row = arow + rr * 64;
            float4 v = *reinterpret_cast<const float4*>(
                A + (size_t)(m0 + row) * K + k0 + avec * 4);
            As[avec * 4 + 0][row] = v.x;
            As[avec * 4 + 1][row] = v.y;
            As[avec * 4 + 2][row] = v.z;
            As[avec * 4 + 3][row] = v.w;
        }
        // W tile 16x64, duplicated: Ws2[k][2n]=Ws2[k][2n+1]=W[k][n]
#pragma unroll
        for (int e = tid; e < 1024; e += 256) {
            int k = e >> 6, n = e & 63;
            float w = W[(size_t)(k0 + k) * NHID + n0 + n];
            Ws2[k][2 * n]     = w;
            Ws2[k][2 * n + 1] = w;
        }
        __syncthreads();

#pragma unroll
        for (int kk = 0; kk < 16; ++kk) {
            ulonglong2 a01 = *reinterpret_cast<const ulonglong2*>(&As [kk][ty * 8]);
            ulonglong2 a23 = *reinterpret_cast<const ulonglong2*>(&As [kk][ty * 8 + 4]);
            ulonglong2 w01 = *reinterpret_cast<const ulonglong2*>(&Ws2[kk][tx * 8]);
            ulonglong2 w23 = *reinterpret_cast<const ulonglong2*>(&Ws2[kk][tx * 8 + 4]);
            u64 ap[4] = {a01.x, a01.y, a23.x, a23.y};
            u64 wp[4] = {w01.x, w01.y, w23.x, w23.y};
#pragma unroll
            for (int p = 0; p < 4; ++p)
#pragma unroll
                for (int c = 0; c < 4; ++c)
                    fma2(acc[p][c], ap[p], wp[c]);
        }
        __syncthreads();
    }

    float4 bias = *reinterpret_cast<const float4*>(b + n0 + tx * 4);
    float bb[4] = {bias.x, bias.y, bias.z, bias.w};
#pragma unroll
    for (int p = 0; p < 4; ++p) {
        float4 lo4, hi4;
        float* lo = reinterpret_cast<float*>(&lo4);
        float* hi = reinterpret_cast<float*>(&hi4);
#pragma unroll
        for (int c = 0; c < 4; ++c) {
            float flo = __uint_as_float((unsigned)(acc[p][c] & 0xffffffffull)) + bb[c];
            float fhi = __uint_as_float((unsigned)(acc[p][c] >> 32)) + bb[c];
            if (RELU) { flo = fmaxf(flo, 0.f); fhi = fmaxf(fhi, 0.f); }
            lo[c] = flo; hi[c] = fhi;
        }
        size_t r0 = (size_t)(m0 + ty * 8 + 2 * p);
        *reinterpret_cast<float4*>(C + r0 * NHID + n0 + tx * 4)       = lo4;
        *reinterpret_cast<float4*>(C + (r0 + 1) * NHID + n0 + tx * 4) = hi4;
    }
}

// ---------------- layer 5 (N=3) + area-weighted combine --------------------
__global__ __launch_bounds__(256)
void final_kernel(const float* __restrict__ H, const float* __restrict__ w5,
                  const float* __restrict__ b5, float* __restrict__ out) {
    __shared__ float w5s[256 * 3];
    const int tid = threadIdx.x;
    for (int i = tid; i < 768; i += 256) w5s[i] = w5[i];
    __syncthreads();

    const int lane = tid & 31;
    const int warp = tid >> 5;
    const int q = blockIdx.x * 8 + warp;

    float pred[4][3];
#pragma unroll
    for (int s = 0; s < 4; ++s) {
        const float* h = H + ((size_t)s * Q + q) * NHID;
        float a0 = 0.f, a1 = 0.f, a2 = 0.f;
#pragma unroll
        for (int r = 0; r < 8; ++r) {
            int k = lane + r * 32;
            float hv = h[k];
            a0 += hv * w5s[k * 3 + 0];
            a1 += hv * w5s[k * 3 + 1];
            a2 += hv * w5s[k * 3 + 2];
        }
#pragma unroll
        for (int o = 16; o; o >>= 1) {
            a0 += __shfl_xor_sync(0xffffffffu, a0, o);
            a1 += __shfl_xor_sync(0xffffffffu, a1, o);
            a2 += __shfl_xor_sync(0xffffffffu, a2, o);
        }
        pred[s][0] = a0; pred[s][1] = a1; pred[s][2] = a2;
    }

    if (lane == 0) {
        float ar[4], tot = 0.f;
#pragma unroll
        for (int s = 0; s < 4; ++s) { ar[s] = g_AREA[(size_t)s * Q + q]; tot += ar[s]; }
        float r[3] = {0.f, 0.f, 0.f};
#pragma unroll
        for (int s = 0; s < 4; ++s) {
            float wgt = ar[3 - s] / tot;
#pragma unroll
            for (int c = 0; c < 3; ++c) r[c] += (pred[s][c] + b5[c]) * wgt;
        }
#pragma unroll
        for (int c = 0; c < 3; ++c) out[(size_t)q * 3 + c] = r[c];
    }
}

// ---------------- launch ----------------------------------------------------
extern "C" void kernel_launch(void* const* d_in, const int* in_sizes, int n_in,
                              void* d_out, int out_size) {
    const float* F    = (const float*)d_in[0];
    const float* loc  = (const float*)d_in[1];
    const float* cell = (const float*)d_in[2];
    const float* w1 = (const float*)d_in[3];
    const float* b1 = (const float*)d_in[4];
    const float* w2 = (const float*)d_in[5];
    const float* b2 = (const float*)d_in[6];
    const float* w3 = (const float*)d_in[7];
    const float* b3 = (const float*)d_in[8];
    const float* w4 = (const float*)d_in[9];
    const float* b4 = (const float*)d_in[10];
    const float* w5 = (const float*)d_in[11];
    const float* b5 = (const float*)d_in[12];
    float* out = (float*)d_out;

    float *X, *HA, *HB, *W1p;
    cudaGetSymbolAddress((void**)&X,   g_X);
    cudaGetSymbolAddress((void**)&HA,  g_HA);
    cudaGetSymbolAddress((void**)&HB,  g_HB);
    cudaGetSymbolAddress((void**)&W1p, g_W1p);

    pad_w1_kernel<<<(K1P * NHID + 255) / 256, 256>>>(w1);
    gather_kernel<<<dim3(Q, 4), 304>>>(F, loc, cell);

    dim3 ggrid(MROWS / 128, NHID / 64);
    gemm_kernel<K1P,  true><<<ggrid, 256>>>(X,  W1p, b1, HA);
    gemm_kernel<NHID, true><<<ggrid, 256>>>(HA, w2,  b2, HB);
    gemm_kernel<NHID, true><<<ggrid, 256>>>(HB, w3,  b3, HA);
    gemm_kernel<NHID, true><<<ggrid, 256>>>(HA, w4,  b4, HB);

    final_kernel<<<Q / 8, 256>>>(HB, w5, b5, out);
}

// round 2
// speedup vs baseline: 1.0007x; 1.0007x over previous
#include <cuda_runtime.h>
#include <cstdint>

#define Q     65536
#define HH    256
#define WW    256
#define CIN   32
#define MROWS (4*Q)      /* 262144 */
#define K1    292
#define K1P   304
#define NHID  256

typedef unsigned long long u64;

// ---------------- scratch (device globals; no allocation allowed) ----------
__device__ float g_X [(size_t)MROWS * K1P];   // ~319 MB
__device__ float g_HA[(size_t)MROWS * NHID];  // ~268 MB
__device__ float g_HB[(size_t)MROWS * NHID];  // ~268 MB
__device__ float g_W1p[K1P * NHID];
__device__ float g_AREA[MROWS];

// ---------------- packed f32x2 FMA (Blackwell FFMA2) -----------------------
__device__ __forceinline__ void fma2(u64 &d, u64 a, u64 b) {
    asm("fma.rn.f32x2 %0, %1, %2, %0;" : "+l"(d) : "l"(a), "l"(b));
}

// ---------------- pad W1 to 304 rows ---------------------------------------
__global__ void pad_w1_kernel(const float* __restrict__ w1) {
    int i = blockIdx.x * 256 + threadIdx.x;
    if (i < K1P * NHID) {
        int k = i / NHID;
        g_W1p[i] = (k < K1) ? w1[(size_t)k * NHID + (i - k * NHID)] : 0.f;
    }
}

// ---------------- gather: build X rows + area weights ----------------------
__global__ void gather_kernel(const float* __restrict__ F,
                              const float* __restrict__ loc,
                              const float* __restrict__ cell) {
    const int q = blockIdx.x;   // query
    const int s = blockIdx.y;   // shift
    const int t = threadIdx.x;  // 0..303

    __shared__ int   s_iy, s_ix;
    __shared__ float s_rel0, s_rel1, s_c0, s_c1;

    if (t == 0) {
        float l0 = loc[(size_t)q * 2 + 0];
        float l1 = loc[(size_t)q * 2 + 1];
        float sy = (s & 2) ? 1.f : -1.f;
        float sx = (s & 1) ? 1.f : -1.f;
        float ly = l0 + sy * (1.f / HH) + 1e-6f;
        float lx = l1 + sx * (1.f / WW) + 1e-6f;
        ly = fminf(fmaxf(ly, -1.f + 1e-6f), 1.f - 1e-6f);
        lx = fminf(fmaxf(lx, -1.f + 1e-6f), 1.f - 1e-6f);
        int iy = (int)rintf(((ly + 1.f) * HH - 1.f) * 0.5f);
        int ix = (int)rintf(((lx + 1.f) * WW - 1.f) * 0.5f);
        iy = min(max(iy, 0), HH - 1);
        ix = min(max(ix, 0), WW - 1);
        float qy = -1.f + (2.f * iy + 1.f) / HH;
        float qx = -1.f + (2.f * ix + 1.f) / WW;
        s_iy = iy; s_ix = ix;
        s_rel0 = (l0 - qy) * HH;
        s_rel1 = (l1 - qx) * WW;
        s_c0 = cell[(size_t)q * 2 + 0] * HH;
        s_c1 = cell[(size_t)q * 2 + 1] * WW;
    }
    __syncthreads();

    const size_t row = (size_t)s * Q + q;
    float v;
    if (t < 288) {
        int c  = t / 9;
        int k  = t - c * 9;
        int di = k / 3;
        int dj = k - di * 3;
        int y = s_iy + di - 1;
        int x = s_ix + dj - 1;
        y = (y < 0) ? -y : ((y >= HH) ? 2 * HH - 2 - y : y);
        x = (x < 0) ? -x : ((x >= WW) ? 2 * WW - 2 - x : x);
        v = F[(size_t)c * (HH * WW) + y * WW + x];
    } else if (t == 288) v = s_rel0;
    else if   (t == 289) v = s_rel1;
    else if   (t == 290) v = s_c0;
    else if   (t == 291) v = s_c1;
    else                 v = 0.f;   // pad cols 292..303

    g_X[row * K1P + t] = v;
    if (t == 288) g_AREA[row] = fabsf(s_rel0 * s_rel1) + 1e-9f;
}

// ---------------- tiled GEMM + bias + ReLU, packed f32x2 -------------------
// C[M,256] = act(A[M,K] @ W[K,256] + b)   BM=128 BN=64 BK=16, 256 thr
template<int K, bool RELU>
__global__ __launch_bounds__(256)
void gemm_kernel(const float* __restrict__ A, const float* __restrict__ W,
                 const float* __restrict__ b, float* __restrict__ C) {
    __shared__ __align__(16) float As [16][128];
    __shared__ __align__(16) float Ws2[16][128];   // W duplicated per column

    const int tid = threadIdx.x;
    const int m0  = blockIdx.x * 128;
    const int n0  = blockIdx.y * 64;
    const int tx  = tid & 15;      // column group -> cols n0 + tx*4 .. +3
    const int ty  = tid >> 4;      // row group    -> rows m0 + ty*8 .. +7

    u64 acc[4][4];
#pragma unroll
    for (int p = 0; p < 4; ++p)
#pragma unroll
        for (int c = 0; c < 4; ++c) acc[p][c] = 0ull;

    const int arow = tid >> 2;     // 0..63
    const int avec = tid & 3;      // float4 idx within 16-wide k

    for (int k0 = 0; k0 < K; k0 += 16) {
        // A tile 128x16 -> As[k][row]
#pragma unroll
        for (int rr = 0; rr < 2; ++rr) {
            int row = arow + rr * 64;
            float4 v = *reinterpret_cast<const float4*>(
                A + (size_t)(m0 + row) * K + k0 + avec * 4);
            As[avec * 4 + 0][row] = v.x;
            As[avec * 4 + 1][row] = v.y;
            As[avec * 4 + 2][row] = v.z;
            As[avec * 4 + 3][row] = v.w;
        }
        // W tile 16x64, duplicated: Ws2[k][2n]=Ws2[k][2n+1]=W[k][n]
#pragma unroll
        for (int e = tid; e < 1024; e += 256) {
            int k = e >> 6, n = e & 63;
            float w = W[(size_t)(k0 + k) * NHID + n0 + n];
            Ws2[k][2 * n]     = w;
            Ws2[k][2 * n + 1] = w;
        }
        __syncthreads();

#pragma unroll
        for (int kk = 0; kk < 16; ++kk) {
            ulonglong2 a01 = *reinterpret_cast<const ulonglong2*>(&As [kk][ty * 8]);
            ulonglong2 a23 = *reinterpret_cast<const ulonglong2*>(&As [kk][ty * 8 + 4]);
            ulonglong2 w01 = *reinterpret_cast<const ulonglong2*>(&Ws2[kk][tx * 8]);
            ulonglong2 w23 = *reinterpret_cast<const ulonglong2*>(&Ws2[kk][tx * 8 + 4]);
            u64 ap[4] = {a01.x, a01.y, a23.x, a23.y};
            u64 wp[4] = {w01.x, w01.y, w23.x, w23.y};
#pragma unroll
            for (int p = 0; p < 4; ++p)
#pragma unroll
                for (int c = 0; c < 4; ++c)
                    fma2(acc[p][c], ap[p], wp[c]);
        }
        __syncthreads();
    }

    float4 bias = *reinterpret_cast<const float4*>(b + n0 + tx * 4);
    float bb[4] = {bias.x, bias.y, bias.z, bias.w};
#pragma unroll
    for (int p = 0; p < 4; ++p) {
        float4 lo4, hi4;
        float* lo = reinterpret_cast<float*>(&lo4);
        float* hi = reinterpret_cast<float*>(&hi4);
#pragma unroll
        for (int c = 0; c < 4; ++c) {
            float flo = __uint_as_float((unsigned)(acc[p][c] & 0xffffffffull)) + bb[c];
            float fhi = __uint_as_float((unsigned)(acc[p][c] >> 32)) + bb[c];
            if (RELU) { flo = fmaxf(flo, 0.f); fhi = fmaxf(fhi, 0.f); }
            lo[c] = flo; hi[c] = fhi;
        }
        size_t r0 = (size_t)(m0 + ty * 8 + 2 * p);
        *reinterpret_cast<float4*>(C + r0 * NHID + n0 + tx * 4)       = lo4;
        *reinterpret_cast<float4*>(C + (r0 + 1) * NHID + n0 + tx * 4) = hi4;
    }
}

// ---------------- layer 5 (N=3) + area-weighted combine --------------------
__global__ __launch_bounds__(256)
void final_kernel(const float* __restrict__ H, const float* __restrict__ w5,
                  const float* __restrict__ b5, float* __restrict__ out) {
    __shared__ float w5s[256 * 3];
    const int tid = threadIdx.x;
    for (int i = tid; i < 768; i += 256) w5s[i] = w5[i];
    __syncthreads();

    const int lane = tid & 31;
    const int warp = tid >> 5;
    const int q = blockIdx.x * 8 + warp;

    float pred[4][3];
#pragma unroll
    for (int s = 0; s < 4; ++s) {
        const float* h = H + ((size_t)s * Q + q) * NHID;
        float a0 = 0.f, a1 = 0.f, a2 = 0.f;
#pragma unroll
        for (int r = 0; r < 8; ++r) {
            int k = lane + r * 32;
            float hv = h[k];
            a0 += hv * w5s[k * 3 + 0];
            a1 += hv * w5s[k * 3 + 1];
            a2 += hv * w5s[k * 3 + 2];
        }
#pragma unroll
        for (int o = 16; o; o >>= 1) {
            a0 += __shfl_xor_sync(0xffffffffu, a0, o);
            a1 += __shfl_xor_sync(0xffffffffu, a1, o);
            a2 += __shfl_xor_sync(0xffffffffu, a2, o);
        }
        pred[s][0] = a0; pred[s][1] = a1; pred[s][2] = a2;
    }

    if (lane == 0) {
        float ar[4], tot = 0.f;
#pragma unroll
        for (int s = 0; s < 4; ++s) { ar[s] = g_AREA[(size_t)s * Q + q]; tot += ar[s]; }
        float r[3] = {0.f, 0.f, 0.f};
#pragma unroll
        for (int s = 0; s < 4; ++s) {
            float wgt = ar[3 - s] / tot;
#pragma unroll
            for (int c = 0; c < 3; ++c) r[c] += (pred[s][c] + b5[c]) * wgt;
        }
#pragma unroll
        for (int c = 0; c < 3; ++c) out[(size_t)q * 3 + c] = r[c];
    }
}

// ---------------- launch ----------------------------------------------------
extern "C" void kernel_launch(void* const* d_in, const int* in_sizes, int n_in,
                              void* d_out, int out_size) {
    const float* F    = (const float*)d_in[0];
    const float* loc  = (const float*)d_in[1];
    const float* cell = (const float*)d_in[2];
    const float* w1 = (const float*)d_in[3];
    const float* b1 = (const float*)d_in[4];
    const float* w2 = (const float*)d_in[5];
    const float* b2 = (const float*)d_in[6];
    const float* w3 = (const float*)d_in[7];
    const float* b3 = (const float*)d_in[8];
    const float* w4 = (const float*)d_in[9];
    const float* b4 = (const float*)d_in[10];
    const float* w5 = (const float*)d_in[11];
    const float* b5 = (const float*)d_in[12];
    float* out = (float*)d_out;

    float *X, *HA, *HB, *W1p;
    cudaGetSymbolAddress((void**)&X,   g_X);
    cudaGetSymbolAddress((void**)&HA,  g_HA);
    cudaGetSymbolAddress((void**)&HB,  g_HB);
    cudaGetSymbolAddress((void**)&W1p, g_W1p);

    pad_w1_kernel<<<(K1P * NHID + 255) / 256, 256>>>(w1);
    gather_kernel<<<dim3(Q, 4), 304>>>(F, loc, cell);

    dim3 ggrid(MROWS / 128, NHID / 64);
    gemm_kernel<K1P,  true><<<ggrid, 256>>>(X,  W1p, b1, HA);
    gemm_kernel<NHID, true><<<ggrid, 256>>>(HA, w2,  b2, HB);
    gemm_kernel<NHID, true><<<ggrid, 256>>>(HB, w3,  b3, HA);
    gemm_kernel<NHID, true><<<ggrid, 256>>>(HA, w4,  b4, HB);

    final_kernel<<<Q / 8, 256>>>(HB, w5, b5, out);
}

// round 4
// speedup vs baseline: 3.1510x; 3.1488x over previous
#include <cuda_runtime.h>
#include <cuda_bf16.h>
#include <cstdint>

#define Q     65536
#define HH    256
#define WW    256
#define MROWS (4*Q)      /* 262144 */
#define K1    292
#define K1P   320        /* 10 k-steps of 32 */
#define NHID  256

typedef unsigned int u32;
typedef unsigned long long u64;

// ---------------- scratch (device globals; no allocation allowed) ----------
__device__ float g_X [(size_t)MROWS * K1P];   // ~335 MB
__device__ float g_HA[(size_t)MROWS * NHID];
__device__ float g_HB[(size_t)MROWS * NHID];
__device__ float g_AREA[MROWS];
__device__ __nv_bfloat16 g_W1h[256 * K1P], g_W1l[256 * K1P];
__device__ __nv_bfloat16 g_W2h[256 * 256], g_W2l[256 * 256];
__device__ __nv_bfloat16 g_W3h[256 * 256], g_W3l[256 * 256];
__device__ __nv_bfloat16 g_W4h[256 * 256], g_W4l[256 * 256];

// ---------------- helpers ---------------------------------------------------
__device__ __forceinline__ u32 pack2(float x, float y) {
    __nv_bfloat162 t = __floats2bfloat162_rn(x, y);
    return *reinterpret_cast<u32*>(&t);
}

__device__ __forceinline__ void mma_bf16(float* d, const u32* a, const u32* b) {
    asm volatile(
        "mma.sync.aligned.m16n8k16.row.col.f32.bf16.bf16.f32 "
        "{%0,%1,%2,%3}, {%4,%5,%6,%7}, {%8,%9}, {%0,%1,%2,%3};"
        : "+f"(d[0]), "+f"(d[1]), "+f"(d[2]), "+f"(d[3])
        : "r"(a[0]), "r"(a[1]), "r"(a[2]), "r"(a[3]), "r"(b[0]), "r"(b[1]));
}

// ---------------- W prep: transpose + pad + bf16 hi/lo split ---------------
__global__ void prep_w_kernel(const float* __restrict__ w, int Ksrc, int Kpad,
                              __nv_bfloat16* __restrict__ hi,
                              __nv_bfloat16* __restrict__ lo) {
    int i = blockIdx.x * 256 + threadIdx.x;
    if (i >= 256 * Kpad) return;
    int n = i / Kpad, k = i - n * Kpad;
    float v = (k < Ksrc) ? w[(size_t)k * 256 + n] : 0.f;
    __nv_bfloat16 h = __float2bfloat16(v);
    hi[i] = h;
    lo[i] = __float2bfloat16(v - __bfloat162float(h));
}

// ---------------- gather: build X rows + area weights ----------------------
__global__ void gather_kernel(const float* __restrict__ F,
                              const float* __restrict__ loc,
                              const float* __restrict__ cell) {
    const int q = blockIdx.x;
    const int s = blockIdx.y;
    const int t = threadIdx.x;  // 0..319

    __shared__ int   s_iy, s_ix;
    __shared__ float s_rel0, s_rel1, s_c0, s_c1;

    if (t == 0) {
        float l0 = loc[(size_t)q * 2 + 0];
        float l1 = loc[(size_t)q * 2 + 1];
        float sy = (s & 2) ? 1.f : -1.f;
        float sx = (s & 1) ? 1.f : -1.f;
        float ly = l0 + sy * (1.f / HH) + 1e-6f;
        float lx = l1 + sx * (1.f / WW) + 1e-6f;
        ly = fminf(fmaxf(ly, -1.f + 1e-6f), 1.f - 1e-6f);
        lx = fminf(fmaxf(lx, -1.f + 1e-6f), 1.f - 1e-6f);
        int iy = (int)rintf(((ly + 1.f) * HH - 1.f) * 0.5f);
        int ix = (int)rintf(((lx + 1.f) * WW - 1.f) * 0.5f);
        iy = min(max(iy, 0), HH - 1);
        ix = min(max(ix, 0), WW - 1);
        float qy = -1.f + (2.f * iy + 1.f) / HH;
        float qx = -1.f + (2.f * ix + 1.f) / WW;
        s_iy = iy; s_ix = ix;
        s_rel0 = (l0 - qy) * HH;
        s_rel1 = (l1 - qx) * WW;
        s_c0 = cell[(size_t)q * 2 + 0] * HH;
        s_c1 = cell[(size_t)q * 2 + 1] * WW;
    }
    __syncthreads();

    const size_t row = (size_t)s * Q + q;
    float v;
    if (t < 288) {
        int c  = t / 9;
        int k  = t - c * 9;
        int di = k / 3;
        int dj = k - di * 3;
        int y = s_iy + di - 1;
        int x = s_ix + dj - 1;
        y = (y < 0) ? -y : ((y >= HH) ? 2 * HH - 2 - y : y);
        x = (x < 0) ? -x : ((x >= WW) ? 2 * WW - 2 - x : x);
        v = F[(size_t)c * (HH * WW) + y * WW + x];
    } else if (t == 288) v = s_rel0;
    else if   (t == 289) v = s_rel1;
    else if   (t == 290) v = s_c0;
    else if   (t == 291) v = s_c1;
    else                 v = 0.f;   // pad cols 292..319

    g_X[row * K1P + t] = v;
    if (t == 288) g_AREA[row] = fabsf(s_rel0 * s_rel1) + 1e-9f;
}

// ---------------- HMMA bf16-3x GEMM + bias + ReLU --------------------------
// C[M,256] = relu(A[M,K] @ W^T + b), tile 128x128, BK=32, 8 warps (4x2)
#define SST 40   /* smem row stride in bf16 (80B, 16B-aligned, conflict-free) */

template<int K>
__global__ __launch_bounds__(256, 2)
void hmma_gemm(const float* __restrict__ A,
               const __nv_bfloat16* __restrict__ Bh,
               const __nv_bfloat16* __restrict__ Bl,
               const float* __restrict__ bias, float* __restrict__ C) {
    __shared__ __align__(16) __nv_bfloat16 sA[2][128 * SST];  // [hi/lo]
    __shared__ __align__(16) __nv_bfloat16 sB[2][128 * SST];

    const int tid  = threadIdx.x;
    const int lane = tid & 31;
    const int wid  = tid >> 5;
    const int wm   = wid & 3;          // warp M index (0..3) -> rows wm*32
    const int wn   = wid >> 2;         // warp N index (0..1) -> cols wn*64
    const int m0   = blockIdx.x * 128;
    const int n0   = blockIdx.y * 128;

    const int lr = lane >> 2;          // 0..7
    const int lq = lane & 3;           // 0..3

    float acc[2][8][4];
#pragma unroll
    for (int i = 0; i < 2; ++i)
#pragma unroll
        for (int j = 0; j < 8; ++j)
#pragma unroll
            for (int c = 0; c < 4; ++c) acc[i][j][c] = 0.f;

    for (int kb = 0; kb < K; kb += 32) {
        // ---- load A tile (fp32 -> bf16 hi/lo) ----
#pragma unroll
        for (int i = 0; i < 4; ++i) {
            int chunk = tid + i * 256;        // 0..1023
            int row = chunk >> 3;             // 0..127
            int c4  = (chunk & 7) << 2;       // 0,4,..,28
            float4 va = *reinterpret_cast<const float4*>(
                A + (size_t)(m0 + row) * K + kb + c4);
            float hx = __bfloat162float(__float2bfloat16(va.x));
            float hy = __bfloat162float(__float2bfloat16(va.y));
            float hz = __bfloat162float(__float2bfloat16(va.z));
            float hw = __bfloat162float(__float2bfloat16(va.w));
            uint2 uh = make_uint2(pack2(hx, hy), pack2(hz, hw));
            uint2 ul = make_uint2(pack2(va.x - hx, va.y - hy),
                                  pack2(va.z - hz, va.w - hw));
            *reinterpret_cast<uint2*>(&sA[0][row * SST + c4]) = uh;
            *reinterpret_cast<uint2*>(&sA[1][row * SST + c4]) = ul;
        }
        // ---- load B tile (pre-split bf16 hi/lo) ----
#pragma unroll
        for (int i = 0; i < 2; ++i) {
            int chunk = tid + i * 256;        // 0..511
            int row = chunk >> 2;             // 0..127
            int c8  = (chunk & 3) << 3;       // 0,8,16,24
            float4 vh = *reinterpret_cast<const float4*>(
                Bh + (size_t)(n0 + row) * K + kb + c8);
            float4 vl = *reinterpret_cast<const float4*>(
                Bl + (size_t)(n0 + row) * K + kb + c8);
            *reinterpret_cast<float4*>(&sB[0][row * SST + c8]) = vh;
            *reinterpret_cast<float4*>(&sB[1][row * SST + c8]) = vl;
        }
        __syncthreads();

#pragma unroll
        for (int ks = 0; ks < 32; ks += 16) {
            const int kcol = ks + lq * 2;
            // A fragments: 2 m-tiles x {hi,lo} x 4 regs
            u32 af[2][2][4];
#pragma unroll
            for (int ti = 0; ti < 2; ++ti) {
                int r = wm * 32 + ti * 16 + lr;
#pragma unroll
                for (int h = 0; h < 2; ++h) {
                    af[ti][h][0] = *reinterpret_cast<const u32*>(&sA[h][(r)     * SST + kcol]);
                    af[ti][h][1] = *reinterpret_cast<const u32*>(&sA[h][(r + 8) * SST + kcol]);
                    af[ti][h][2] = *reinterpret_cast<const u32*>(&sA[h][(r)     * SST + kcol + 8]);
                    af[ti][h][3] = *reinterpret_cast<const u32*>(&sA[h][(r + 8) * SST + kcol + 8]);
                }
            }
#pragma unroll
            for (int tj = 0; tj < 8; ++tj) {
                int cn = wn * 64 + tj * 8 + lr;
                u32 bfh[2], bfl[2];
                bfh[0] = *reinterpret_cast<const u32*>(&sB[0][cn * SST + kcol]);
                bfh[1] = *reinterpret_cast<const u32*>(&sB[0][cn * SST + kcol + 8]);
                bfl[0] = *reinterpret_cast<const u32*>(&sB[1][cn * SST + kcol]);
                bfl[1] = *reinterpret_cast<const u32*>(&sB[1][cn * SST + kcol + 8]);
#pragma unroll
                for (int ti = 0; ti < 2; ++ti) {
                    mma_bf16(acc[ti][tj], af[ti][0], bfh);  // Ah*Bh
                    mma_bf16(acc[ti][tj], af[ti][0], bfl);  // Ah*Bl
                    mma_bf16(acc[ti][tj], af[ti][1], bfh);  // Al*Bh
                }
            }
        }
        __syncthreads();
    }

    // ---- epilogue: bias + relu + store ----
#pragma unroll
    for (int ti = 0; ti < 2; ++ti) {
        int row0 = m0 + wm * 32 + ti * 16 + lr;
#pragma unroll
        for (int tj = 0; tj < 8; ++tj) {
            int col0 = n0 + wn * 64 + tj * 8 + lq * 2;
            float b0 = bias[col0], b1 = bias[col0 + 1];
            float2 v0 = make_float2(fmaxf(acc[ti][tj][0] + b0, 0.f),
                                    fmaxf(acc[ti][tj][1] + b1, 0.f));
            float2 v1 = make_float2(fmaxf(acc[ti][tj][2] + b0, 0.f),
                                    fmaxf(acc[ti][tj][3] + b1, 0.f));
            *reinterpret_cast<float2*>(C + (size_t)row0 * NHID + col0)       = v0;
            *reinterpret_cast<float2*>(C + (size_t)(row0 + 8) * NHID + col0) = v1;
        }
    }
}

// ---------------- layer 5 (N=3) + area-weighted combine --------------------
__global__ __launch_bounds__(256)
void final_kernel(const float* __restrict__ H, const float* __restrict__ w5,
                  const float* __restrict__ b5, float* __restrict__ out) {
    __shared__ float w5s[256 * 3];
    const int tid = threadIdx.x;
    for (int i = tid; i < 768; i += 256) w5s[i] = w5[i];
    __syncthreads();

    const int lane = tid & 31;
    const int warp = tid >> 5;
    const int q = blockIdx.x * 8 + warp;

    float pred[4][3];
#pragma unroll
    for (int s = 0; s < 4; ++s) {
        const float* h = H + ((size_t)s * Q + q) * NHID;
        float a0 = 0.f, a1 = 0.f, a2 = 0.f;
#pragma unroll
        for (int r = 0; r < 8; ++r) {
            int k = lane + r * 32;
            float hv = h[k];
            a0 += hv * w5s[k * 3 + 0];
            a1 += hv * w5s[k * 3 + 1];
            a2 += hv * w5s[k * 3 + 2];
        }
#pragma unroll
        for (int o = 16; o; o >>= 1) {
            a0 += __shfl_xor_sync(0xffffffffu, a0, o);
            a1 += __shfl_xor_sync(0xffffffffu, a1, o);
            a2 += __shfl_xor_sync(0xffffffffu, a2, o);
        }
        pred[s][0] = a0; pred[s][1] = a1; pred[s][2] = a2;
    }

    if (lane == 0) {
        float ar[4], tot = 0.f;
#pragma unroll
        for (int s = 0; s < 4; ++s) { ar[s] = g_AREA[(size_t)s * Q + q]; tot += ar[s]; }
        float r[3] = {0.f, 0.f, 0.f};
#pragma unroll
        for (int s = 0; s < 4; ++s) {
            float wgt = ar[3 - s] / tot;
#pragma unroll
            for (int c = 0; c < 3; ++c) r[c] += (pred[s][c] + b5[c]) * wgt;
        }
#pragma unroll
        for (int c = 0; c < 3; ++c) out[(size_t)q * 3 + c] = r[c];
    }
}

// ---------------- launch ----------------------------------------------------
extern "C" void kernel_launch(void* const* d_in, const int* in_sizes, int n_in,
                              void* d_out, int out_size) {
    const float* F    = (const float*)d_in[0];
    const float* loc  = (const float*)d_in[1];
    const float* cell = (const float*)d_in[2];
    const float* w1 = (const float*)d_in[3];
    const float* b1 = (const float*)d_in[4];
    const float* w2 = (const float*)d_in[5];
    const float* b2 = (const float*)d_in[6];
    const float* w3 = (const float*)d_in[7];
    const float* b3 = (const float*)d_in[8];
    const float* w4 = (const float*)d_in[9];
    const float* b4 = (const float*)d_in[10];
    const float* w5 = (const float*)d_in[11];
    const float* b5 = (const float*)d_in[12];
    float* out = (float*)d_out;

    float *X, *HA, *HB;
    __nv_bfloat16 *W1h, *W1l, *W2h, *W2l, *W3h, *W3l, *W4h, *W4l;
    cudaGetSymbolAddress((void**)&X,  g_X);
    cudaGetSymbolAddress((void**)&HA, g_HA);
    cudaGetSymbolAddress((void**)&HB, g_HB);
    cudaGetSymbolAddress((void**)&W1h, g_W1h); cudaGetSymbolAddress((void**)&W1l, g_W1l);
    cudaGetSymbolAddress((void**)&W2h, g_W2h); cudaGetSymbolAddress((void**)&W2l, g_W2l);
    cudaGetSymbolAddress((void**)&W3h, g_W3h); cudaGetSymbolAddress((void**)&W3l, g_W3l);
    cudaGetSymbolAddress((void**)&W4h, g_W4h); cudaGetSymbolAddress((void**)&W4l, g_W4l);

    prep_w_kernel<<<(256 * K1P + 255) / 256, 256>>>(w1, K1, K1P, W1h, W1l);
    prep_w_kernel<<<(256 * 256 + 255) / 256, 256>>>(w2, 256, 256, W2h, W2l);
    prep_w_kernel<<<(256 * 256 + 255) / 256, 256>>>(w3, 256, 256, W3h, W3l);
    prep_w_kernel<<<(256 * 256 + 255) / 256, 256>>>(w4, 256, 256, W4h, W4l);

    gather_kernel<<<dim3(Q, 4), K1P>>>(F, loc, cell);

    dim3 ggrid(MROWS / 128, NHID / 128);
    hmma_gemm<K1P><<<ggrid, 256>>>(X,  W1h, W1l, b1, HA);
    hmma_gemm<256><<<ggrid, 256>>>(HA, W2h, W2l, b2, HB);
    hmma_gemm<256><<<ggrid, 256>>>(HB, W3h, W3l, b3, HA);
    hmma_gemm<256><<<ggrid, 256>>>(HA, W4h, W4l, b4, HB);

    final_kernel<<<Q / 8, 256>>>(HB, w5, b5, out);
}